// round 2
// baseline (speedup 1.0000x reference)
#include <cuda_runtime.h>
#include <math.h>

#define NBLK 148
#define NTHR 1024
#define CHUNK_B 4                 // batches per chunk (4 * 16MB = 64MB, fits L2)
#define NCHUNK 4
#define ROWS_PER_CHUNK (CHUNK_B * 16 * 64)        // 4096 pooled rows per chunk
#define F4_PER_CHUNK   (ROWS_PER_CHUNK * 1024)    // 4,194,304 float4 per chunk

// Scratch (allocation-free rule: __device__ globals)
__device__ float g_pooled[16 * 16 * 64];
__device__ float g_delta [16 * 16 * 64];

// Software grid barrier state. Must end each launch at initial values
// (count=0, sense=0): 8 barriers per launch -> even number of sense flips.
__device__ unsigned int          g_bar_count = 0;
__device__ volatile unsigned int g_bar_sense = 0;

__device__ __forceinline__ void grid_sync(unsigned int& sense) {
    __syncthreads();
    if (threadIdx.x == 0) {
        sense ^= 1u;
        __threadfence();                       // publish this block's prior writes
        if (atomicAdd(&g_bar_count, 1u) == NBLK - 1u) {
            g_bar_count = 0;                   // reset for next barrier
            __threadfence();
            g_bar_sense = sense;               // release
        } else {
            while (g_bar_sense != sense) { }   // spin on L2
        }
        __threadfence();                       // acquire
    }
    __syncthreads();
}

__global__ void __launch_bounds__(NTHR, 1)
fused_kernel(const float* __restrict__ x,
             float* __restrict__ out,
             const float* __restrict__ compress_w,   // [4,64]
             const float* __restrict__ compress_b,   // [4]
             const float* __restrict__ in_proj_w,    // [12,4]
             const float* __restrict__ in_proj_b,    // [12]
             const float* __restrict__ out_proj_w,   // [4,4]
             const float* __restrict__ out_proj_b,   // [4]
             const float* __restrict__ expand_w,     // [64,4]
             const float* __restrict__ expand_b,     // [64]
             const float* __restrict__ ln_w,         // [64]
             const float* __restrict__ ln_b,         // [64]
             const float* __restrict__ gate)         // [1]
{
    const int tid  = threadIdx.x;
    const int lane = tid & 31;
    const int wid  = tid >> 5;
    const int gwarp = blockIdx.x * (NTHR >> 5) + wid;   // 0..4735
    unsigned int sense = 0;

    __shared__ float sp[16][64];    // pooled (residual)
    __shared__ float sxc[16][4];    // compressed
    __shared__ float sqkv[16][12];  // q|k|v
    __shared__ float so[16][4];     // attention output
    __shared__ float sat[16][4];    // out_proj output
    __shared__ float sy[16][64];    // residual + gate*expand

    for (int c = 0; c < NCHUNK; c++) {
        // ---------------- Phase 1: pool chunk c (lines land in L2) ----------
        if (gwarp < ROWS_PER_CHUNK) {
            const int row = c * ROWS_PER_CHUNK + gwarp;
            const float4* p = reinterpret_cast<const float4*>(x + (size_t)row * 4096);
            float s = 0.f;
            #pragma unroll 8
            for (int j = lane; j < 1024; j += 32) {
                const float4 v = p[j];
                s += (v.x + v.y) + (v.z + v.w);
            }
            #pragma unroll
            for (int o = 16; o > 0; o >>= 1)
                s += __shfl_down_sync(0xffffffffu, s, o);
            if (lane == 0)
                g_pooled[row] = s * (1.0f / 4096.0f);
        }
        grid_sync(sense);

        // ---------------- Phase 2: mid math, blocks 0..3, batch each --------
        if (blockIdx.x < CHUNK_B) {
            const int b = c * CHUNK_B + blockIdx.x;

            if (tid < 1024)
                sp[tid >> 6][tid & 63] = g_pooled[b * 1024 + tid];
            __syncthreads();

            // compress: [16,64] @ [64->4]
            if (tid < 64) {
                const int l = tid >> 2, e = tid & 3;
                float s = compress_b[e];
                #pragma unroll
                for (int j = 0; j < 64; j++) s += sp[l][j] * compress_w[e * 64 + j];
                sxc[l][e] = s;
            }
            __syncthreads();

            // qkv: [16,4] @ [4->12]
            if (tid < 192) {
                const int l = tid / 12, r = tid % 12;
                float s = in_proj_b[r];
                #pragma unroll
                for (int e = 0; e < 4; e++) s += sxc[l][e] * in_proj_w[r * 4 + e];
                sqkv[l][r] = s;
            }
            __syncthreads();

            // attention: 2 heads, dh=2, L=16
            if (tid < 32) {
                const int h = tid >> 4, q = tid & 15;
                const int d0 = h * 2, d1 = h * 2 + 1;
                const float scale = 0.70710678118654752440f; // 1/sqrt(2)
                float sc[16], m = -1e30f;
                #pragma unroll
                for (int j = 0; j < 16; j++) {
                    const float v = (sqkv[q][d0] * sqkv[j][4 + d0] +
                                     sqkv[q][d1] * sqkv[j][4 + d1]) * scale;
                    sc[j] = v;
                    m = fmaxf(m, v);
                }
                float denom = 0.f;
                #pragma unroll
                for (int j = 0; j < 16; j++) { sc[j] = __expf(sc[j] - m); denom += sc[j]; }
                const float inv = 1.0f / denom;
                float o0 = 0.f, o1 = 0.f;
                #pragma unroll
                for (int j = 0; j < 16; j++) {
                    const float a = sc[j] * inv;
                    o0 += a * sqkv[j][8 + d0];
                    o1 += a * sqkv[j][8 + d1];
                }
                so[q][d0] = o0;
                so[q][d1] = o1;
            }
            __syncthreads();

            // out_proj: [16,4] @ [4->4]
            if (tid < 64) {
                const int l = tid >> 2, e = tid & 3;
                float s = out_proj_b[e];
                #pragma unroll
                for (int j = 0; j < 4; j++) s += so[l][j] * out_proj_w[e * 4 + j];
                sat[l][e] = s;
            }
            __syncthreads();

            // expand + residual + gate
            {
                const float g = gate[0];
                const int l = tid >> 6, cc = tid & 63;
                float s = expand_b[cc];
                #pragma unroll
                for (int j = 0; j < 4; j++) s += sat[l][j] * expand_w[cc * 4 + j];
                sy[l][cc] = sp[l][cc] + g * s;
            }
            __syncthreads();

            // LayerNorm over hd=64, delta = ln_out - residual
            if (tid < 16) {
                const int l = tid;
                float mu = 0.f;
                #pragma unroll
                for (int k = 0; k < 64; k++) mu += sy[l][k];
                mu *= (1.0f / 64.0f);
                float var = 0.f;
                #pragma unroll
                for (int k = 0; k < 64; k++) {
                    const float d = sy[l][k] - mu;
                    var += d * d;
                }
                var *= (1.0f / 64.0f);
                const float inv = rsqrtf(var + 1e-5f);
                #pragma unroll
                for (int k = 0; k < 64; k++) {
                    const float o = (sy[l][k] - mu) * inv * ln_w[k] + ln_b[k];
                    g_delta[b * 1024 + l * 64 + k] = o - sp[l][k];
                }
            }
            __syncthreads();
        }
        grid_sync(sense);

        // ---------------- Phase 3: add (x re-read should hit L2) ------------
        {
            const size_t base = (size_t)c * F4_PER_CHUNK;
            const float4* xin = reinterpret_cast<const float4*>(x);
            float4* oo = reinterpret_cast<float4*>(out);
            for (int i = blockIdx.x * NTHR + tid; i < F4_PER_CHUNK; i += NBLK * NTHR) {
                const size_t i4 = base + (size_t)i;
                const float d = g_delta[i4 >> 10];   // 1024 float4 per pooled row
                float4 v = xin[i4];
                v.x += d; v.y += d; v.z += d; v.w += d;
                __stcs(oo + i4, v);                  // streaming store, evict-first
            }
        }
        // next iteration's pool has no data dependence on this add, but the
        // grid_sync at the top of the next chunk's phase-2 orders everything.
    }
}

extern "C" void kernel_launch(void* const* d_in, const int* in_sizes, int n_in,
                              void* d_out, int out_size) {
    const float* x          = (const float*)d_in[0];
    const float* compress_w = (const float*)d_in[1];
    const float* compress_b = (const float*)d_in[2];
    const float* in_proj_w  = (const float*)d_in[3];
    const float* in_proj_b  = (const float*)d_in[4];
    const float* out_proj_w = (const float*)d_in[5];
    const float* out_proj_b = (const float*)d_in[6];
    const float* expand_w   = (const float*)d_in[7];
    const float* expand_b   = (const float*)d_in[8];
    const float* ln_w       = (const float*)d_in[9];
    const float* ln_b       = (const float*)d_in[10];
    const float* gate       = (const float*)d_in[11];
    float* out = (float*)d_out;

    fused_kernel<<<NBLK, NTHR>>>(x, out,
                                 compress_w, compress_b, in_proj_w, in_proj_b,
                                 out_proj_w, out_proj_b, expand_w, expand_b,
                                 ln_w, ln_b, gate);
}

// round 3
// speedup vs baseline: 1.2421x; 1.2421x over previous
#include <cuda_runtime.h>
#include <math.h>

// Scratch (allocation-free rule: __device__ globals)
__device__ float g_pooled[16 * 16 * 64];   // [B][nH][hd]
__device__ float g_delta [16 * 16 * 64];   // [B][nH][hd]

// ---------------------------------------------------------------------------
// Kernel 1: mean-pool over H*W (4096 contiguous floats per row).
// One warp per row. 8 warps / block -> 2048 blocks of 256 threads.
// ---------------------------------------------------------------------------
__global__ void pool_kernel(const float* __restrict__ x) {
    const int warp_id = (blockIdx.x << 3) + (threadIdx.x >> 5);
    const int lane = threadIdx.x & 31;

    const float4* row = reinterpret_cast<const float4*>(x) + ((size_t)warp_id << 10);
    float s = 0.f;
    #pragma unroll 8
    for (int j = lane; j < 1024; j += 32) {
        const float4 v = __ldcs(row + j);
        s += (v.x + v.y) + (v.z + v.w);
    }
    #pragma unroll
    for (int o = 16; o > 0; o >>= 1)
        s += __shfl_down_sync(0xffffffffu, s, o);
    if (lane == 0)
        g_pooled[warp_id] = s * (1.0f / 4096.0f);
}

// ---------------------------------------------------------------------------
// Kernel 2: compress -> MHA (2 heads, L=16, E=4) -> out_proj -> expand ->
//           residual+gate -> LayerNorm -> delta.  One block per batch b.
// ---------------------------------------------------------------------------
__global__ void mid_kernel(const float* __restrict__ compress_w,   // [4,64]
                           const float* __restrict__ compress_b,   // [4]
                           const float* __restrict__ in_proj_w,    // [12,4]
                           const float* __restrict__ in_proj_b,    // [12]
                           const float* __restrict__ out_proj_w,   // [4,4]
                           const float* __restrict__ out_proj_b,   // [4]
                           const float* __restrict__ expand_w,     // [64,4]
                           const float* __restrict__ expand_b,     // [64]
                           const float* __restrict__ ln_w,         // [64]
                           const float* __restrict__ ln_b,         // [64]
                           const float* __restrict__ gate)         // [1]
{
    const int b = blockIdx.x;     // 0..15
    const int tid = threadIdx.x;  // 0..127

    __shared__ float sp[16][64];    // pooled (residual)
    __shared__ float sxc[16][4];    // compressed
    __shared__ float sqkv[16][12];  // q|k|v
    __shared__ float so[16][4];     // attention output
    __shared__ float sat[16][4];    // out_proj output
    __shared__ float sy[16][64];    // residual + gate*expand

    // load pooled
    for (int i = tid; i < 1024; i += 128)
        sp[i >> 6][i & 63] = g_pooled[b * 1024 + i];
    __syncthreads();

    // compress: [16,64] @ [64->4]
    if (tid < 64) {
        const int l = tid >> 2, e = tid & 3;
        float s = compress_b[e];
        #pragma unroll
        for (int j = 0; j < 64; j++) s += sp[l][j] * compress_w[e * 64 + j];
        sxc[l][e] = s;
    }
    __syncthreads();

    // qkv projection: [16,4] @ [4->12]
    for (int idx = tid; idx < 192; idx += 128) {
        const int l = idx / 12, r = idx % 12;
        float s = in_proj_b[r];
        #pragma unroll
        for (int e = 0; e < 4; e++) s += sxc[l][e] * in_proj_w[r * 4 + e];
        sqkv[l][r] = s;
    }
    __syncthreads();

    // attention: 2 heads, dh=2, L=16. One thread per (head, query).
    if (tid < 32) {
        const int h = tid >> 4, q = tid & 15;
        const int d0 = h * 2, d1 = h * 2 + 1;
        const float scale = 0.70710678118654752440f; // 1/sqrt(2)
        float sc[16], m = -1e30f;
        #pragma unroll
        for (int j = 0; j < 16; j++) {
            float v = (sqkv[q][d0] * sqkv[j][4 + d0] +
                       sqkv[q][d1] * sqkv[j][4 + d1]) * scale;
            sc[j] = v;
            m = fmaxf(m, v);
        }
        float denom = 0.f;
        #pragma unroll
        for (int j = 0; j < 16; j++) { sc[j] = __expf(sc[j] - m); denom += sc[j]; }
        const float inv = 1.0f / denom;
        float o0 = 0.f, o1 = 0.f;
        #pragma unroll
        for (int j = 0; j < 16; j++) {
            const float a = sc[j] * inv;
            o0 += a * sqkv[j][8 + d0];
            o1 += a * sqkv[j][8 + d1];
        }
        so[q][d0] = o0;
        so[q][d1] = o1;
    }
    __syncthreads();

    // out_proj: [16,4] @ [4->4]
    if (tid < 64) {
        const int l = tid >> 2, e = tid & 3;
        float s = out_proj_b[e];
        #pragma unroll
        for (int j = 0; j < 4; j++) s += so[l][j] * out_proj_w[e * 4 + j];
        sat[l][e] = s;
    }
    __syncthreads();

    // expand + residual + gate
    const float g = gate[0];
    for (int i = tid; i < 1024; i += 128) {
        const int l = i >> 6, c = i & 63;
        float s = expand_b[c];
        #pragma unroll
        for (int j = 0; j < 4; j++) s += sat[l][j] * expand_w[c * 4 + j];
        sy[l][c] = sp[l][c] + g * s;
    }
    __syncthreads();

    // LayerNorm over hd=64, then delta = ln_out - residual
    if (tid < 16) {
        const int l = tid;
        float mu = 0.f;
        #pragma unroll
        for (int c = 0; c < 64; c++) mu += sy[l][c];
        mu *= (1.0f / 64.0f);
        float var = 0.f;
        #pragma unroll
        for (int c = 0; c < 64; c++) {
            const float d = sy[l][c] - mu;
            var += d * d;
        }
        var *= (1.0f / 64.0f);
        const float inv = rsqrtf(var + 1e-5f);
        #pragma unroll
        for (int c = 0; c < 64; c++) {
            const float o = (sy[l][c] - mu) * inv * ln_w[c] + ln_b[c];
            g_delta[b * 1024 + l * 64 + c] = o - sp[l][c];
        }
    }
}

// ---------------------------------------------------------------------------
// Kernel 3: out = x + delta[row]. One block per pooled row (16384 blocks,
// 256 threads); each thread handles 4 float4 with all loads issued first
// (MLP=4), streaming loads + streaming stores.
// ---------------------------------------------------------------------------
__global__ void __launch_bounds__(256)
add_kernel(const float* __restrict__ x, float* __restrict__ out) {
    const int row = blockIdx.x;                       // 0..16383
    const float d = g_delta[row];                     // uniform per block
    const size_t base = ((size_t)row << 10) + threadIdx.x;  // float4 units
    const float4* xin = reinterpret_cast<const float4*>(x) + base;
    float4* oo = reinterpret_cast<float4*>(out) + base;

    float4 v0 = __ldcs(xin);
    float4 v1 = __ldcs(xin + 256);
    float4 v2 = __ldcs(xin + 512);
    float4 v3 = __ldcs(xin + 768);

    v0.x += d; v0.y += d; v0.z += d; v0.w += d;
    v1.x += d; v1.y += d; v1.z += d; v1.w += d;
    v2.x += d; v2.y += d; v2.z += d; v2.w += d;
    v3.x += d; v3.y += d; v3.z += d; v3.w += d;

    __stcs(oo,       v0);
    __stcs(oo + 256, v1);
    __stcs(oo + 512, v2);
    __stcs(oo + 768, v3);
}

extern "C" void kernel_launch(void* const* d_in, const int* in_sizes, int n_in,
                              void* d_out, int out_size) {
    const float* x          = (const float*)d_in[0];
    const float* compress_w = (const float*)d_in[1];
    const float* compress_b = (const float*)d_in[2];
    const float* in_proj_w  = (const float*)d_in[3];
    const float* in_proj_b  = (const float*)d_in[4];
    const float* out_proj_w = (const float*)d_in[5];
    const float* out_proj_b = (const float*)d_in[6];
    const float* expand_w   = (const float*)d_in[7];
    const float* expand_b   = (const float*)d_in[8];
    const float* ln_w       = (const float*)d_in[9];
    const float* ln_b       = (const float*)d_in[10];
    const float* gate       = (const float*)d_in[11];
    float* out = (float*)d_out;

    // 1) pool: 16384 rows, 1 warp each, 8 warps/block
    pool_kernel<<<2048, 256>>>(x);

    // 2) tiny middle math: 1 block per batch
    mid_kernel<<<16, 128>>>(compress_w, compress_b, in_proj_w, in_proj_b,
                            out_proj_w, out_proj_b, expand_w, expand_b,
                            ln_w, ln_b, gate);

    // 3) broadcast add: one block per pooled row
    add_kernel<<<16384, 256>>>(x, out);
}

// round 4
// speedup vs baseline: 1.2829x; 1.0329x over previous
#include <cuda_runtime.h>
#include <math.h>

// Scratch (allocation-free rule: __device__ globals)
__device__ float g_pooled[16 * 16 * 64];   // [B][nH][hd]
__device__ float g_delta [16 * 16 * 64];   // [B][nH][hd]

// ---------------------------------------------------------------------------
// Kernel 1: mean-pool over H*W (4096 contiguous floats per row).
// One warp per row. 8 warps / block -> 2048 blocks of 256 threads.
// DEFAULT-cached loads: the ~126MB tail of x stays L2-resident for kernel 3.
// ---------------------------------------------------------------------------
__global__ void pool_kernel(const float* __restrict__ x) {
    const int warp_id = (blockIdx.x << 3) + (threadIdx.x >> 5);
    const int lane = threadIdx.x & 31;

    const float4* row = reinterpret_cast<const float4*>(x) + ((size_t)warp_id << 10);
    float s = 0.f;
    #pragma unroll 8
    for (int j = lane; j < 1024; j += 32) {
        const float4 v = row[j];            // default policy -> lines linger in L2
        s += (v.x + v.y) + (v.z + v.w);
    }
    #pragma unroll
    for (int o = 16; o > 0; o >>= 1)
        s += __shfl_down_sync(0xffffffffu, s, o);
    if (lane == 0)
        g_pooled[warp_id] = s * (1.0f / 4096.0f);
}

// ---------------------------------------------------------------------------
// Kernel 2: compress -> MHA (2 heads, L=16, E=4) -> out_proj -> expand ->
//           residual+gate -> LayerNorm -> delta.  One block per batch b.
// ---------------------------------------------------------------------------
__global__ void mid_kernel(const float* __restrict__ compress_w,   // [4,64]
                           const float* __restrict__ compress_b,   // [4]
                           const float* __restrict__ in_proj_w,    // [12,4]
                           const float* __restrict__ in_proj_b,    // [12]
                           const float* __restrict__ out_proj_w,   // [4,4]
                           const float* __restrict__ out_proj_b,   // [4]
                           const float* __restrict__ expand_w,     // [64,4]
                           const float* __restrict__ expand_b,     // [64]
                           const float* __restrict__ ln_w,         // [64]
                           const float* __restrict__ ln_b,         // [64]
                           const float* __restrict__ gate)         // [1]
{
    const int b = blockIdx.x;     // 0..15
    const int tid = threadIdx.x;  // 0..127

    __shared__ float sp[16][64];    // pooled (residual)
    __shared__ float sxc[16][4];    // compressed
    __shared__ float sqkv[16][12];  // q|k|v
    __shared__ float so[16][4];     // attention output
    __shared__ float sat[16][4];    // out_proj output
    __shared__ float sy[16][64];    // residual + gate*expand

    // load pooled
    for (int i = tid; i < 1024; i += 128)
        sp[i >> 6][i & 63] = g_pooled[b * 1024 + i];
    __syncthreads();

    // compress: [16,64] @ [64->4]
    if (tid < 64) {
        const int l = tid >> 2, e = tid & 3;
        float s = compress_b[e];
        #pragma unroll
        for (int j = 0; j < 64; j++) s += sp[l][j] * compress_w[e * 64 + j];
        sxc[l][e] = s;
    }
    __syncthreads();

    // qkv projection: [16,4] @ [4->12]
    for (int idx = tid; idx < 192; idx += 128) {
        const int l = idx / 12, r = idx % 12;
        float s = in_proj_b[r];
        #pragma unroll
        for (int e = 0; e < 4; e++) s += sxc[l][e] * in_proj_w[r * 4 + e];
        sqkv[l][r] = s;
    }
    __syncthreads();

    // attention: 2 heads, dh=2, L=16. One thread per (head, query).
    if (tid < 32) {
        const int h = tid >> 4, q = tid & 15;
        const int d0 = h * 2, d1 = h * 2 + 1;
        const float scale = 0.70710678118654752440f; // 1/sqrt(2)
        float sc[16], m = -1e30f;
        #pragma unroll
        for (int j = 0; j < 16; j++) {
            float v = (sqkv[q][d0] * sqkv[j][4 + d0] +
                       sqkv[q][d1] * sqkv[j][4 + d1]) * scale;
            sc[j] = v;
            m = fmaxf(m, v);
        }
        float denom = 0.f;
        #pragma unroll
        for (int j = 0; j < 16; j++) { sc[j] = __expf(sc[j] - m); denom += sc[j]; }
        const float inv = 1.0f / denom;
        float o0 = 0.f, o1 = 0.f;
        #pragma unroll
        for (int j = 0; j < 16; j++) {
            const float a = sc[j] * inv;
            o0 += a * sqkv[j][8 + d0];
            o1 += a * sqkv[j][8 + d1];
        }
        so[q][d0] = o0;
        so[q][d1] = o1;
    }
    __syncthreads();

    // out_proj: [16,4] @ [4->4]
    if (tid < 64) {
        const int l = tid >> 2, e = tid & 3;
        float s = out_proj_b[e];
        #pragma unroll
        for (int j = 0; j < 4; j++) s += so[l][j] * out_proj_w[e * 4 + j];
        sat[l][e] = s;
    }
    __syncthreads();

    // expand + residual + gate
    const float g = gate[0];
    for (int i = tid; i < 1024; i += 128) {
        const int l = i >> 6, c = i & 63;
        float s = expand_b[c];
        #pragma unroll
        for (int j = 0; j < 4; j++) s += sat[l][j] * expand_w[c * 4 + j];
        sy[l][c] = sp[l][c] + g * s;
    }
    __syncthreads();

    // LayerNorm over hd=64, then delta = ln_out - residual
    if (tid < 16) {
        const int l = tid;
        float mu = 0.f;
        #pragma unroll
        for (int c = 0; c < 64; c++) mu += sy[l][c];
        mu *= (1.0f / 64.0f);
        float var = 0.f;
        #pragma unroll
        for (int c = 0; c < 64; c++) {
            const float d = sy[l][c] - mu;
            var += d * d;
        }
        var *= (1.0f / 64.0f);
        const float inv = rsqrtf(var + 1e-5f);
        #pragma unroll
        for (int c = 0; c < 64; c++) {
            const float o = (sy[l][c] - mu) * inv * ln_w[c] + ln_b[c];
            g_delta[b * 1024 + l * 64 + c] = o - sp[l][c];
        }
    }
}

// ---------------------------------------------------------------------------
// Kernel 3: out = x + delta[row]. One block per pooled row, processed in
// REVERSE row order so the first-scheduled blocks read the x tail that
// pool_kernel just left resident in L2. MLP=4 loads, streaming stores.
// ---------------------------------------------------------------------------
__global__ void __launch_bounds__(256)
add_kernel(const float* __restrict__ x, float* __restrict__ out) {
    const int row = 16383 - blockIdx.x;               // reverse order: hot tail first
    const float d = g_delta[row];                     // uniform per block
    const size_t base = ((size_t)row << 10) + threadIdx.x;  // float4 units
    const float4* xin = reinterpret_cast<const float4*>(x) + base;
    float4* oo = reinterpret_cast<float4*>(out) + base;

    float4 v0 = __ldcg(xin);
    float4 v1 = __ldcg(xin + 256);
    float4 v2 = __ldcg(xin + 512);
    float4 v3 = __ldcg(xin + 768);

    v0.x += d; v0.y += d; v0.z += d; v0.w += d;
    v1.x += d; v1.y += d; v1.z += d; v1.w += d;
    v2.x += d; v2.y += d; v2.z += d; v2.w += d;
    v3.x += d; v3.y += d; v3.z += d; v3.w += d;

    __stcs(oo,       v0);
    __stcs(oo + 256, v1);
    __stcs(oo + 512, v2);
    __stcs(oo + 768, v3);
}

extern "C" void kernel_launch(void* const* d_in, const int* in_sizes, int n_in,
                              void* d_out, int out_size) {
    const float* x          = (const float*)d_in[0];
    const float* compress_w = (const float*)d_in[1];
    const float* compress_b = (const float*)d_in[2];
    const float* in_proj_w  = (const float*)d_in[3];
    const float* in_proj_b  = (const float*)d_in[4];
    const float* out_proj_w = (const float*)d_in[5];
    const float* out_proj_b = (const float*)d_in[6];
    const float* expand_w   = (const float*)d_in[7];
    const float* expand_b   = (const float*)d_in[8];
    const float* ln_w       = (const float*)d_in[9];
    const float* ln_b       = (const float*)d_in[10];
    const float* gate       = (const float*)d_in[11];
    float* out = (float*)d_out;

    // 1) pool: 16384 rows, 1 warp each, 8 warps/block
    pool_kernel<<<2048, 256>>>(x);

    // 2) tiny middle math: 1 block per batch
    mid_kernel<<<16, 128>>>(compress_w, compress_b, in_proj_w, in_proj_b,
                            out_proj_w, out_proj_b, expand_w, expand_b,
                            ln_w, ln_b, gate);

    // 3) broadcast add: one block per pooled row, reverse order
    add_kernel<<<16384, 256>>>(x, out);
}